// round 2
// baseline (speedup 1.0000x reference)
#include <cuda_runtime.h>
#include <math.h>

#define BSZ 8
#define NB  8
#define MM  512
#define DD  128
#define NN  1024
#define NBK 64
#define NEGV (-1e30f)

// output layout (element offsets into d_out):
//   y_em    (8,1024,8,128) = 8388608
//   delta_em(8,1024,8,128) = 8388608
//   new_K   (8,8,512,128)  = 4194304
//   new_V   (8,8,512,128)  = 4194304
//   new_S   (8,8,512)      = 32768
//   new_age (8,8,512)      = 32768
#define OFF_YEM 0
#define OFF_DEM 8388608
#define OFF_K   16777216
#define OFF_V   20971520
#define OFF_S   25165824
#define OFF_AGE 25198592

// ---------------- scratch (device globals; no allocations allowed) --------
__device__ float g_y[NBK * NN * DD];        // (bk, n, d)
__device__ float g_attn[NBK * NN * MM];     // (bk, n, m)   attn / nov_attn
__device__ float g_route[NBK * NN * MM];    // (bk, n, m)   route softmax
__device__ float g_wnorm[BSZ * NN * DD];    // (b, n, d)
__device__ float g_surp[BSZ * NN];          // (b, n)
__device__ float g_nov[NBK * NN];           // (bk, n) novelty_bn
__device__ float g_sumwr[NBK * MM];         // (bk, m) sum_n weighted_route
__device__ float g_updK[NBK * MM * DD];     // raw (pre-denom) update_K
__device__ float g_updV[NBK * MM * DD];

// ---------------- helpers --------------------------------------------------
__device__ __forceinline__ void fma2(float2 &d, float2 a, float2 b) {
    asm("fma.rn.f32x2 %0, %1, %2, %0;"
        : "+l"(*reinterpret_cast<unsigned long long *>(&d))
        : "l"(*reinterpret_cast<unsigned long long *>(&a)),
          "l"(*reinterpret_cast<unsigned long long *>(&b)));
}
__device__ __forceinline__ float softplusf(float x) {
    return (x > 20.f) ? x : log1pf(expf(x));
}
__device__ __forceinline__ float sigmoidf(float x) {
    return 1.f / (1.f + __expf(-x));
}

// ---------------- y init: y[bk,n,d] = seed[b,n,d] --------------------------
__global__ void init_y_kernel(const float *__restrict__ seed) {
    int i = blockIdx.x * 256 + threadIdx.x;      // float4 index, 2097152 total
    int bk = i >> 15;                            // 32768 float4 per bk
    int rem = i & 32767;
    int b = bk >> 3;
    reinterpret_cast<float4 *>(g_y)[i] =
        reinterpret_cast<const float4 *>(seed)[b * 32768 + rem];
}

// ---------------- w_norm + surprise magnitude ------------------------------
__global__ void wnorm_kernel(const float *__restrict__ wc,
                             const float *__restrict__ sp) {
    int row = blockIdx.x;              // b*NN + n, 8192 rows
    int tid = threadIdx.x;             // 128
    float w = wc[row * DD + tid];
    float s = sp[row * DD + tid];
    float a = w * w, bb = s * s;
#pragma unroll
    for (int o = 16; o; o >>= 1) {
        a  += __shfl_xor_sync(0xffffffffu, a, o);
        bb += __shfl_xor_sync(0xffffffffu, bb, o);
    }
    __shared__ float ra[4], rb[4];
    if ((tid & 31) == 0) { ra[tid >> 5] = a; rb[tid >> 5] = bb; }
    __syncthreads();
    float na = ra[0] + ra[1] + ra[2] + ra[3];
    float nb = rb[0] + rb[1] + rb[2] + rb[3];
    g_wnorm[row * DD + tid] = w / fmaxf(sqrtf(na), 1e-12f);
    if (tid == 0) g_surp[row] = sqrtf(nb);
}

// ---------------- scores GEMM + masked softmax ------------------------------
// MODE 0: Y = g_y,     one softmax (scale 1/tau, *has)        -> g_attn
// MODE 1: Y = g_wnorm, pass0: nov_attn (1/tau, *has) -> g_attn
//                      pass1: route    (1/tau_w, no has)      -> g_route
// block: 32 n-rows x full M=512. threads 256 = 8 warps; warp = 4 rows.
template <int MODE>
__global__ __launch_bounds__(256) void scores_kernel(
    const float *__restrict__ emK, const float *__restrict__ emS,
    const float *__restrict__ rtau, const float *__restrict__ rtauw) {
    __shared__ __align__(16) float As[32][18];
    __shared__ __align__(16) float Bs[16][514];
    int bk = blockIdx.y, b = bk >> 3, k = bk & 7;
    int n0 = blockIdx.x * 32;
    int tid = threadIdx.x, ty = tid >> 5, tx = tid & 31;

    const float *Yb = (MODE == 0) ? (g_y + (size_t)bk * NN * DD)
                                  : (g_wnorm + (size_t)b * NN * DD);
    const float *Kb = emK + (size_t)bk * MM * DD;

    float2 acc[4][8];
#pragma unroll
    for (int r = 0; r < 4; r++)
#pragma unroll
        for (int c = 0; c < 8; c++) acc[r][c] = make_float2(0.f, 0.f);

    for (int dc = 0; dc < 8; dc++) {
        int d0 = dc * 16;
        {   // A chunk: 32 rows x 16 d
            int row = tid >> 3, dl = (tid & 7) * 2;
            float2 v = *reinterpret_cast<const float2 *>(
                &Yb[(n0 + row) * DD + d0 + dl]);
            As[row][dl] = v.x; As[row][dl + 1] = v.y;
        }
#pragma unroll
        for (int i = 0; i < 8; i++) {   // B chunk transposed: 16 d x 512 m
            int idx = tid + i * 256;
            int m = idx >> 2, q = idx & 3;
            float4 v = *reinterpret_cast<const float4 *>(
                &Kb[m * DD + d0 + q * 4]);
            Bs[q * 4 + 0][m] = v.x; Bs[q * 4 + 1][m] = v.y;
            Bs[q * 4 + 2][m] = v.z; Bs[q * 4 + 3][m] = v.w;
        }
        __syncthreads();
#pragma unroll
        for (int kk = 0; kk < 16; kk++) {
            float a0 = As[ty * 4 + 0][kk], a1 = As[ty * 4 + 1][kk];
            float a2 = As[ty * 4 + 2][kk], a3 = As[ty * 4 + 3][kk];
#pragma unroll
            for (int c = 0; c < 8; c++) {
                float2 bv = *reinterpret_cast<const float2 *>(
                    &Bs[kk][tx * 2 + c * 64]);
                fma2(acc[0][c], make_float2(a0, a0), bv);
                fma2(acc[1][c], make_float2(a1, a1), bv);
                fma2(acc[2][c], make_float2(a2, a2), bv);
                fma2(acc[3][c], make_float2(a3, a3), bv);
            }
        }
        __syncthreads();
    }
    // ---- epilogue: per-row masked softmax (each row fully inside one warp)
    float inv_tau  = 1.f / (softplusf(rtau[k]) + 0.1f);
    float inv_tauw = 1.f / (softplusf(rtauw[k]) + 0.1f);
    const float *Sb = emS + bk * MM;
    bool actx[8], acty[8]; bool myany = false;
#pragma unroll
    for (int c = 0; c < 8; c++) {
        int m = tx * 2 + c * 64;
        actx[c] = Sb[m] > 0.f; acty[c] = Sb[m + 1] > 0.f;
        myany |= actx[c] | acty[c];
    }
    float has = __any_sync(0xffffffffu, myany) ? 1.f : 0.f;

    int np = (MODE == 1) ? 2 : 1;
    for (int p = 0; p < np; p++) {
        float sc = (p == 0) ? inv_tau : inv_tauw;
        float hm = (p == 0) ? has : 1.f;
        float *op = (p == 0) ? g_attn : g_route;
#pragma unroll
        for (int r = 0; r < 4; r++) {
            float vx[8], vy[8];
            float mx = NEGV;
#pragma unroll
            for (int c = 0; c < 8; c++) {
                vx[c] = actx[c] ? acc[r][c].x * sc : NEGV;
                vy[c] = acty[c] ? acc[r][c].y * sc : NEGV;
                mx = fmaxf(mx, fmaxf(vx[c], vy[c]));
            }
#pragma unroll
            for (int o = 16; o; o >>= 1)
                mx = fmaxf(mx, __shfl_xor_sync(0xffffffffu, mx, o));
            float sum = 0.f;
#pragma unroll
            for (int c = 0; c < 8; c++) {
                vx[c] = __expf(vx[c] - mx);
                vy[c] = __expf(vy[c] - mx);
                sum += vx[c] + vy[c];
            }
#pragma unroll
            for (int o = 16; o; o >>= 1)
                sum += __shfl_xor_sync(0xffffffffu, sum, o);
            float f = hm / sum;
            int rowoff = (bk * NN + n0 + ty * 4 + r) * MM;
#pragma unroll
            for (int c = 0; c < 8; c++)
                *reinterpret_cast<float2 *>(&op[rowoff + tx * 2 + c * 64]) =
                    make_float2(vx[c] * f, vy[c] * f);
        }
    }
}

// ---------------- A@V GEMM ---------------------------------------------------
// MODE 0: step (not last) -> gate update, write g_y
// MODE 1: step (last)     -> gate update, write y_em output
// MODE 2: recon           -> recon_err -> novelty, delta_em output, g_nov
// block: 64 n-rows x full D=128, loop m. threads 256: ty=tid/16 (4 rows each),
// tx=tid%16 (8 d each as 4 float2).
template <int MODE>
__global__ __launch_bounds__(256) void av_kernel(
    const float *__restrict__ emV, const float *__restrict__ w1,
    const float *__restrict__ w2, const float *__restrict__ gb,
    const float *__restrict__ seed, const float *__restrict__ wcand,
    float *__restrict__ out) {
    __shared__ __align__(16) float As2[64][36];
    __shared__ __align__(16) float Vs[32][132];
    __shared__ float rownov[64];
    int bk = blockIdx.y, b = bk >> 3, k = bk & 7;
    int n0 = blockIdx.x * 64;
    int tid = threadIdx.x, ty = tid >> 4, tx = tid & 15;
    const float *Ab = g_attn + (size_t)bk * NN * MM;
    const float *Vb = emV + (size_t)bk * MM * DD;

    float2 acc[4][4];
#pragma unroll
    for (int r = 0; r < 4; r++)
#pragma unroll
        for (int c = 0; c < 4; c++) acc[r][c] = make_float2(0.f, 0.f);

    for (int m0 = 0; m0 < MM; m0 += 32) {
#pragma unroll
        for (int i = 0; i < 2; i++) {   // A: 64 x 32
            int idx = tid + i * 256;
            int row = idx >> 3, q = idx & 7;
            float4 v = *reinterpret_cast<const float4 *>(
                &Ab[(n0 + row) * MM + m0 + q * 4]);
            *reinterpret_cast<float4 *>(&As2[row][q * 4]) = v;
        }
#pragma unroll
        for (int i = 0; i < 4; i++) {   // V: 32 x 128
            int idx = tid + i * 256;
            int mm = idx >> 5, q = idx & 31;
            float4 v = *reinterpret_cast<const float4 *>(
                &Vb[(m0 + mm) * DD + q * 4]);
            *reinterpret_cast<float4 *>(&Vs[mm][q * 4]) = v;
        }
        __syncthreads();
#pragma unroll
        for (int mm = 0; mm < 32; mm++) {
            float a0 = As2[ty * 4 + 0][mm], a1 = As2[ty * 4 + 1][mm];
            float a2 = As2[ty * 4 + 2][mm], a3 = As2[ty * 4 + 3][mm];
#pragma unroll
            for (int c = 0; c < 4; c++) {
                float2 v = *reinterpret_cast<const float2 *>(
                    &Vs[mm][tx * 2 + c * 32]);
                fma2(acc[0][c], make_float2(a0, a0), v);
                fma2(acc[1][c], make_float2(a1, a1), v);
                fma2(acc[2][c], make_float2(a2, a2), v);
                fma2(acc[3][c], make_float2(a3, a3), v);
            }
        }
        __syncthreads();
    }

    if (MODE == 0 || MODE == 1) {
        const float *w1k = w1 + k * DD, *w2k = w2 + k * DD, *gbk = gb + k * DD;
#pragma unroll
        for (int r = 0; r < 4; r++) {
            int n = n0 + ty * 4 + r;
            size_t yb = ((size_t)bk * NN + n) * DD;
#pragma unroll
            for (int c = 0; c < 4; c++) {
                int d = tx * 2 + c * 32;
                float2 del = acc[r][c];
                float2 yo = *reinterpret_cast<const float2 *>(&g_y[yb + d]);
                float2 w1v = *reinterpret_cast<const float2 *>(&w1k[d]);
                float2 w2v = *reinterpret_cast<const float2 *>(&w2k[d]);
                float2 gbv = *reinterpret_cast<const float2 *>(&gbk[d]);
                float gx = sigmoidf(w1v.x * yo.x + w2v.x * del.x + gbv.x);
                float gy = sigmoidf(w1v.y * yo.y + w2v.y * del.y + gbv.y);
                float2 yn = make_float2(yo.x + gx * del.x, yo.y + gy * del.y);
                if (MODE == 0) {
                    *reinterpret_cast<float2 *>(&g_y[yb + d]) = yn;
                } else {
                    float2 sd = *reinterpret_cast<const float2 *>(
                        &seed[((size_t)b * NN + n) * DD + d]);
                    *reinterpret_cast<float2 *>(
                        &out[OFF_YEM + (((size_t)b * NN + n) * NB + k) * DD + d]) =
                        make_float2(yn.x - sd.x, yn.y - sd.y);
                }
            }
        }
    } else {  // MODE 2: recon epilogue
        float2 wcv[4][4];
        float psq[4] = {0.f, 0.f, 0.f, 0.f};
#pragma unroll
        for (int r = 0; r < 4; r++) {
            int n = n0 + ty * 4 + r;
#pragma unroll
            for (int c = 0; c < 4; c++) {
                int d = tx * 2 + c * 32;
                float2 w = *reinterpret_cast<const float2 *>(
                    &wcand[((size_t)b * NN + n) * DD + d]);
                wcv[r][c] = w;
                float rx = w.x - acc[r][c].x;
                float ry = w.y - acc[r][c].y;
                psq[r] += rx * rx + ry * ry;
            }
        }
#pragma unroll
        for (int r = 0; r < 4; r++)
#pragma unroll
            for (int o = 8; o; o >>= 1)
                psq[r] += __shfl_xor_sync(0xffffffffu, psq[r], o);
        if (tx == 0) {
#pragma unroll
            for (int r = 0; r < 4; r++) {
                int n = n0 + ty * 4 + r;
                float err = sqrtf(psq[r]);
                float nv = 0.5f * g_surp[b * NN + n] + 0.5f * err;
                rownov[ty * 4 + r] = nv;
                g_nov[bk * NN + n] = nv;
            }
        }
        __syncthreads();
#pragma unroll
        for (int r = 0; r < 4; r++) {
            int n = n0 + ty * 4 + r;
            float nv = rownov[ty * 4 + r];
#pragma unroll
            for (int c = 0; c < 4; c++) {
                int d = tx * 2 + c * 32;
                *reinterpret_cast<float2 *>(
                    &out[OFF_DEM + (((size_t)b * NN + n) * NB + k) * DD + d]) =
                    make_float2(nv * wcv[r][c].x, nv * wcv[r][c].y);
            }
        }
    }
}

// ---------------- update_K / update_V GEMM (wr^T @ W) + sum_n wr -------------
// C[m,d] = sum_n (nov[n]*route[n,m]) * W[n,d]; block: 64 m-rows x D=128.
__global__ __launch_bounds__(256) void updkv_kernel(
    const float *__restrict__ wcand) {
    __shared__ __align__(16) float WRs[32][68];
    __shared__ __align__(16) float Wn[32][132];
    __shared__ __align__(16) float Wc[32][132];
    __shared__ float novS[32];
    int bk = blockIdx.y, b = bk >> 3;
    int m0 = blockIdx.x * 64;
    int tid = threadIdx.x, ty = tid >> 4, tx = tid & 15;

    float2 aK[4][4], aV[4][4];
    float swr[4] = {0.f, 0.f, 0.f, 0.f};
#pragma unroll
    for (int r = 0; r < 4; r++)
#pragma unroll
        for (int c = 0; c < 4; c++) {
            aK[r][c] = make_float2(0.f, 0.f);
            aV[r][c] = make_float2(0.f, 0.f);
        }

    for (int n0 = 0; n0 < NN; n0 += 32) {
        if (tid < 32) novS[tid] = g_nov[bk * NN + n0 + tid];
#pragma unroll
        for (int i = 0; i < 2; i++) {   // route tile 32n x 64m
            int idx = tid + i * 256;
            int nn = idx >> 4, q = idx & 15;
            float4 v = *reinterpret_cast<const float4 *>(
                &g_route[((size_t)bk * NN + n0 + nn) * MM + m0 + q * 4]);
            *reinterpret_cast<float4 *>(&WRs[nn][q * 4]) = v;
        }
#pragma unroll
        for (int i = 0; i < 4; i++) {   // wnorm / wcand tiles 32n x 128d
            int idx = tid + i * 256;
            int nn = idx >> 5, q = idx & 31;
            size_t base = ((size_t)b * NN + n0 + nn) * DD + q * 4;
            *reinterpret_cast<float4 *>(&Wn[nn][q * 4]) =
                *reinterpret_cast<const float4 *>(&g_wnorm[base]);
            *reinterpret_cast<float4 *>(&Wc[nn][q * 4]) =
                *reinterpret_cast<const float4 *>(&wcand[base]);
        }
        __syncthreads();
#pragma unroll 8
        for (int nn = 0; nn < 32; nn++) {
            float nv = novS[nn];
            float a0 = WRs[nn][ty * 4 + 0] * nv;
            float a1 = WRs[nn][ty * 4 + 1] * nv;
            float a2 = WRs[nn][ty * 4 + 2] * nv;
            float a3 = WRs[nn][ty * 4 + 3] * nv;
            swr[0] += a0; swr[1] += a1; swr[2] += a2; swr[3] += a3;
#pragma unroll
            for (int c = 0; c < 4; c++) {
                float2 wn = *reinterpret_cast<const float2 *>(
                    &Wn[nn][tx * 2 + c * 32]);
                float2 wc = *reinterpret_cast<const float2 *>(
                    &Wc[nn][tx * 2 + c * 32]);
                fma2(aK[0][c], make_float2(a0, a0), wn);
                fma2(aK[1][c], make_float2(a1, a1), wn);
                fma2(aK[2][c], make_float2(a2, a2), wn);
                fma2(aK[3][c], make_float2(a3, a3), wn);
                fma2(aV[0][c], make_float2(a0, a0), wc);
                fma2(aV[1][c], make_float2(a1, a1), wc);
                fma2(aV[2][c], make_float2(a2, a2), wc);
                fma2(aV[3][c], make_float2(a3, a3), wc);
            }
        }
        __syncthreads();
    }
#pragma unroll
    for (int r = 0; r < 4; r++) {
        int m = m0 + ty * 4 + r;
#pragma unroll
        for (int c = 0; c < 4; c++) {
            int d = tx * 2 + c * 32;
            *reinterpret_cast<float2 *>(&g_updK[((size_t)bk * MM + m) * DD + d]) = aK[r][c];
            *reinterpret_cast<float2 *>(&g_updV[((size_t)bk * MM + m) * DD + d]) = aV[r][c];
        }
        if (tx == 0) g_sumwr[bk * MM + m] = swr[r];
    }
}

// ---------------- final: blend K/V, S budget, age ---------------------------
__global__ __launch_bounds__(256) void final_kernel(
    const float *__restrict__ emK, const float *__restrict__ emV,
    const float *__restrict__ emS, const float *__restrict__ emAge,
    const float *__restrict__ gem, float *__restrict__ out) {
    int bk = blockIdx.x, b = bk >> 3, k = bk & 7;
    int tid = threadIdx.x, warp = tid >> 5, lane = tid & 31;
    float ge = gem[b * NB + k];
    const float invN = 1.f / (float)NN;

    for (int m = warp; m < MM; m += 8) {
        float swv = g_sumwr[bk * MM + m];
        float denom = fmaxf(swv, 1e-8f);
        float alpha = fminf(ge * swv * invN, 1.f);
        float oma = 1.f - alpha;
        float idn = 1.f / denom;
        size_t off = ((size_t)bk * MM + m) * DD + lane * 4;
        float4 uk = *reinterpret_cast<const float4 *>(&g_updK[off]);
        uk.x *= idn; uk.y *= idn; uk.z *= idn; uk.w *= idn;
        float sq = uk.x * uk.x + uk.y * uk.y + uk.z * uk.z + uk.w * uk.w;
#pragma unroll
        for (int o = 16; o; o >>= 1) sq += __shfl_xor_sync(0xffffffffu, sq, o);
        float inv = 1.f / fmaxf(sqrtf(sq), 1e-12f);
        float ai = alpha * inv;
        float4 ek = *reinterpret_cast<const float4 *>(&emK[off]);
        float4 nk = make_float4(oma * ek.x + ai * uk.x, oma * ek.y + ai * uk.y,
                                oma * ek.z + ai * uk.z, oma * ek.w + ai * uk.w);
        *reinterpret_cast<float4 *>(&out[OFF_K + off]) = nk;
        float4 uv = *reinterpret_cast<const float4 *>(&g_updV[off]);
        uv.x *= idn; uv.y *= idn; uv.z *= idn; uv.w *= idn;
        float4 ev = *reinterpret_cast<const float4 *>(&emV[off]);
        float4 nv = make_float4(oma * ev.x + alpha * uv.x, oma * ev.y + alpha * uv.y,
                                oma * ev.z + alpha * uv.z, oma * ev.w + alpha * uv.w);
        *reinterpret_cast<float4 *>(&out[OFF_V + off]) = nv;
    }

    __shared__ float red[8];
    __shared__ float stot;
    float part = 0.f, sn[2], al[2];
#pragma unroll
    for (int i = 0; i < 2; i++) {
        int m = tid + i * 256;
        float swv = g_sumwr[bk * MM + m];
        al[i] = fminf(ge * swv * invN, 1.f);
        float v = emS[bk * MM + m] + al[i];
        v = fminf(fmaxf(v, 0.f), 3.0f);
        sn[i] = v; part += v;
    }
#pragma unroll
    for (int o = 16; o; o >>= 1) part += __shfl_xor_sync(0xffffffffu, part, o);
    if (lane == 0) red[warp] = part;
    __syncthreads();
    if (tid == 0) {
        float t = 0.f;
        for (int i = 0; i < 8; i++) t += red[i];
        stot = t;
    }
    __syncthreads();
    float scale = fminf(1.f, 32.0f / fmaxf(stot, 1e-8f));
#pragma unroll
    for (int i = 0; i < 2; i++) {
        int m = tid + i * 256;
        out[OFF_S + bk * MM + m] = sn[i] * scale;
        out[OFF_AGE + bk * MM + m] = emAge[bk * MM + m] * (1.f - al[i]);
    }
}

// ---------------- launcher ---------------------------------------------------
extern "C" void kernel_launch(void *const *d_in, const int *in_sizes, int n_in,
                              void *d_out, int out_size) {
    const float *seed     = (const float *)d_in[0];
    const float *wcand    = (const float *)d_in[1];
    const float *surprise = (const float *)d_in[2];
    const float *gem      = (const float *)d_in[3];
    const float *emK      = (const float *)d_in[4];
    const float *emV      = (const float *)d_in[5];
    const float *emS      = (const float *)d_in[6];
    const float *emAge    = (const float *)d_in[7];
    const float *w1       = (const float *)d_in[8];
    const float *w2       = (const float *)d_in[9];
    const float *gb       = (const float *)d_in[10];
    const float *rtau     = (const float *)d_in[11];
    const float *rtauw    = (const float *)d_in[12];
    float *out = (float *)d_out;

    dim3 gA(32, 64), gB(16, 64), gU(8, 64);

    init_y_kernel<<<8192, 256>>>(seed);
    wnorm_kernel<<<8192, 128>>>(wcand, surprise);

    // step 0
    scores_kernel<0><<<gA, 256>>>(emK, emS, rtau, rtauw);
    av_kernel<0><<<gB, 256>>>(emV, w1, w2, gb, seed, wcand, out);
    // step 1 (last)
    scores_kernel<0><<<gA, 256>>>(emK, emS, rtau, rtauw);
    av_kernel<1><<<gB, 256>>>(emV, w1, w2, gb, seed, wcand, out);

    // novelty: raw scores -> nov_attn + route
    scores_kernel<1><<<gA, 256>>>(emK, emS, rtau, rtauw);
    // recon + novelty + delta_em
    av_kernel<2><<<gB, 256>>>(emV, w1, w2, gb, seed, wcand, out);
    // update_K / update_V (+ sum_n weighted_route)
    updkv_kernel<<<gU, 256>>>(wcand);
    // final blend / budget
    final_kernel<<<64, 256>>>(emK, emV, emS, emAge, gem, out);
}

// round 3
// speedup vs baseline: 1.0132x; 1.0132x over previous
#include <cuda_runtime.h>
#include <math.h>

#define BSZ 8
#define NB  8
#define MM  512
#define DD  128
#define NN  1024
#define NBK 64
#define NEGV (-1e30f)

#define OFF_YEM 0
#define OFF_DEM 8388608
#define OFF_K   16777216
#define OFF_V   20971520
#define OFF_S   25165824
#define OFF_AGE 25198592

// ---------------- scratch ---------------------------------------------------
__device__ float g_y[NBK * NN * DD];
__device__ float g_attn[NBK * NN * MM];
__device__ float g_route[NBK * NN * MM];
__device__ float g_wnorm[BSZ * NN * DD];
__device__ float g_surp[BSZ * NN];
__device__ float g_nov[NBK * NN];
__device__ float g_sumwr[NBK * MM];
__device__ float g_updK[NBK * MM * DD];
__device__ float g_updV[NBK * MM * DD];
__device__ float g_Kt[NBK * DD * MM];      // em_K transposed: (bk, d, m)

// ---------------- helpers ---------------------------------------------------
__device__ __forceinline__ void fma2(float2 &d, float2 a, float2 b) {
    asm("fma.rn.f32x2 %0, %1, %2, %0;"
        : "+l"(*reinterpret_cast<unsigned long long *>(&d))
        : "l"(*reinterpret_cast<unsigned long long *>(&a)),
          "l"(*reinterpret_cast<unsigned long long *>(&b)));
}
__device__ __forceinline__ float softplusf(float x) {
    return (x > 20.f) ? x : log1pf(expf(x));
}
__device__ __forceinline__ float sigmoidf(float x) {
    return 1.f / (1.f + __expf(-x));
}

// ---------------- K transpose: g_Kt[bk][d][m] = emK[bk][m][d] ---------------
__global__ void transpose_k_kernel(const float *__restrict__ emK) {
    __shared__ float t[32][33];
    int bk = blockIdx.z;
    int m0 = blockIdx.x * 32, d0 = blockIdx.y * 32;
    int x = threadIdx.x, y0 = threadIdx.y;       // 32 x 8
#pragma unroll
    for (int yy = 0; yy < 32; yy += 8)
        t[y0 + yy][x] = emK[((size_t)bk * MM + m0 + y0 + yy) * DD + d0 + x];
    __syncthreads();
#pragma unroll
    for (int yy = 0; yy < 32; yy += 8)
        g_Kt[((size_t)bk * DD + d0 + y0 + yy) * MM + m0 + x] = t[x][y0 + yy];
}

// ---------------- y init -----------------------------------------------------
__global__ void init_y_kernel(const float *__restrict__ seed) {
    int i = blockIdx.x * 256 + threadIdx.x;
    int bk = i >> 15;
    int rem = i & 32767;
    int b = bk >> 3;
    reinterpret_cast<float4 *>(g_y)[i] =
        reinterpret_cast<const float4 *>(seed)[b * 32768 + rem];
}

// ---------------- w_norm + surprise magnitude --------------------------------
__global__ void wnorm_kernel(const float *__restrict__ wc,
                             const float *__restrict__ sp) {
    int row = blockIdx.x;
    int tid = threadIdx.x;
    float w = wc[row * DD + tid];
    float s = sp[row * DD + tid];
    float a = w * w, bb = s * s;
#pragma unroll
    for (int o = 16; o; o >>= 1) {
        a  += __shfl_xor_sync(0xffffffffu, a, o);
        bb += __shfl_xor_sync(0xffffffffu, bb, o);
    }
    __shared__ float ra[4], rb[4];
    if ((tid & 31) == 0) { ra[tid >> 5] = a; rb[tid >> 5] = bb; }
    __syncthreads();
    float na = ra[0] + ra[1] + ra[2] + ra[3];
    float nb = rb[0] + rb[1] + rb[2] + rb[3];
    g_wnorm[row * DD + tid] = w / fmaxf(sqrtf(na), 1e-12f);
    if (tid == 0) g_surp[row] = sqrtf(nb);
}

// ---------------- scores GEMM + masked softmax --------------------------------
// 32 n-rows x full M=512 per block. warp = 4 rows; lane covers m = tx*4+c*128+j.
template <int MODE>
__global__ __launch_bounds__(256, 2) void scores_kernel(
    const float *__restrict__ emS,
    const float *__restrict__ rtau, const float *__restrict__ rtauw) {
    __shared__ __align__(16) float AsT[16][36];      // [d][row]
    __shared__ __align__(16) float Bs[16][520];      // [d][m]
    int bk = blockIdx.y, b = bk >> 3, k = bk & 7;
    int n0 = blockIdx.x * 32;
    int tid = threadIdx.x, ty = tid >> 5, tx = tid & 31;

    const float *Yb = (MODE == 0) ? (g_y + (size_t)bk * NN * DD)
                                  : (g_wnorm + (size_t)b * NN * DD);
    const float *Ktb = g_Kt + (size_t)bk * DD * MM;

    float2 acc[4][8];
#pragma unroll
    for (int r = 0; r < 4; r++)
#pragma unroll
        for (int c = 0; c < 8; c++) acc[r][c] = make_float2(0.f, 0.f);

    for (int dc = 0; dc < 8; dc++) {
        int d0 = dc * 16;
        {   // A chunk 32 rows x 16 d -> transposed
            int row = tid >> 3, dl = (tid & 7) * 2;
            float2 v = *reinterpret_cast<const float2 *>(
                &Yb[(n0 + row) * DD + d0 + dl]);
            AsT[dl][row] = v.x; AsT[dl + 1][row] = v.y;
        }
#pragma unroll
        for (int i = 0; i < 8; i++) {   // B chunk 16 d x 512 m, direct float4
            int idx = tid + i * 256;
            int q = idx >> 7, mq = idx & 127;
            float4 v = *reinterpret_cast<const float4 *>(
                &Ktb[(size_t)(d0 + q) * MM + mq * 4]);
            *reinterpret_cast<float4 *>(&Bs[q][mq * 4]) = v;
        }
        __syncthreads();
#pragma unroll
        for (int kk = 0; kk < 16; kk++) {
            float4 a4 = *reinterpret_cast<const float4 *>(&AsT[kk][ty * 4]);
#pragma unroll
            for (int c = 0; c < 4; c++) {
                float4 bv = *reinterpret_cast<const float4 *>(
                    &Bs[kk][tx * 4 + c * 128]);
                float2 blo = make_float2(bv.x, bv.y);
                float2 bhi = make_float2(bv.z, bv.w);
                fma2(acc[0][c * 2],     make_float2(a4.x, a4.x), blo);
                fma2(acc[0][c * 2 + 1], make_float2(a4.x, a4.x), bhi);
                fma2(acc[1][c * 2],     make_float2(a4.y, a4.y), blo);
                fma2(acc[1][c * 2 + 1], make_float2(a4.y, a4.y), bhi);
                fma2(acc[2][c * 2],     make_float2(a4.z, a4.z), blo);
                fma2(acc[2][c * 2 + 1], make_float2(a4.z, a4.z), bhi);
                fma2(acc[3][c * 2],     make_float2(a4.w, a4.w), blo);
                fma2(acc[3][c * 2 + 1], make_float2(a4.w, a4.w), bhi);
            }
        }
        __syncthreads();
    }
    // ---- epilogue: masked softmax per row (row fully inside one warp)
    float inv_tau  = 1.f / (softplusf(rtau[k]) + 0.1f);
    float inv_tauw = 1.f / (softplusf(rtauw[k]) + 0.1f);
    const float *Sb = emS + bk * MM;
    bool act[4][4]; bool myany = false;
#pragma unroll
    for (int c = 0; c < 4; c++) {
        float4 s4 = *reinterpret_cast<const float4 *>(&Sb[tx * 4 + c * 128]);
        act[c][0] = s4.x > 0.f; act[c][1] = s4.y > 0.f;
        act[c][2] = s4.z > 0.f; act[c][3] = s4.w > 0.f;
        myany |= act[c][0] | act[c][1] | act[c][2] | act[c][3];
    }
    float has = __any_sync(0xffffffffu, myany) ? 1.f : 0.f;

    int np = (MODE == 1) ? 2 : 1;
    for (int p = 0; p < np; p++) {
        float sc = (p == 0) ? inv_tau : inv_tauw;
        float hm = (p == 0) ? has : 1.f;
        float *op = (p == 0) ? g_attn : g_route;
#pragma unroll
        for (int r = 0; r < 4; r++) {
            float v[16];
#pragma unroll
            for (int c = 0; c < 4; c++) {
                v[c * 4 + 0] = act[c][0] ? acc[r][c * 2].x     * sc : NEGV;
                v[c * 4 + 1] = act[c][1] ? acc[r][c * 2].y     * sc : NEGV;
                v[c * 4 + 2] = act[c][2] ? acc[r][c * 2 + 1].x * sc : NEGV;
                v[c * 4 + 3] = act[c][3] ? acc[r][c * 2 + 1].y * sc : NEGV;
            }
            float mx = NEGV;
#pragma unroll
            for (int j = 0; j < 16; j++) mx = fmaxf(mx, v[j]);
#pragma unroll
            for (int o = 16; o; o >>= 1)
                mx = fmaxf(mx, __shfl_xor_sync(0xffffffffu, mx, o));
            float sum = 0.f;
#pragma unroll
            for (int j = 0; j < 16; j++) { v[j] = __expf(v[j] - mx); sum += v[j]; }
#pragma unroll
            for (int o = 16; o; o >>= 1)
                sum += __shfl_xor_sync(0xffffffffu, sum, o);
            float f = hm / sum;
            size_t rowoff = ((size_t)bk * NN + n0 + ty * 4 + r) * MM;
#pragma unroll
            for (int c = 0; c < 4; c++)
                *reinterpret_cast<float4 *>(&op[rowoff + tx * 4 + c * 128]) =
                    make_float4(v[c * 4] * f, v[c * 4 + 1] * f,
                                v[c * 4 + 2] * f, v[c * 4 + 3] * f);
        }
    }
}

// ---------------- A@V GEMM ----------------------------------------------------
// 64 n-rows x D=128 per block. ty=tid/16 -> 4 rows, tx=tid%16 -> d=tx*4+c*64.
template <int MODE>
__global__ __launch_bounds__(256) void av_kernel(
    const float *__restrict__ emV, const float *__restrict__ w1,
    const float *__restrict__ w2, const float *__restrict__ gb,
    const float *__restrict__ seed, const float *__restrict__ wcand,
    float *__restrict__ out) {
    __shared__ __align__(16) float AsT[32][68];    // [m][row]
    __shared__ __align__(16) float Vs[32][132];    // [m][d]
    __shared__ float rownov[64];
    int bk = blockIdx.y, b = bk >> 3, k = bk & 7;
    int n0 = blockIdx.x * 64;
    int tid = threadIdx.x, ty = tid >> 4, tx = tid & 15;
    const float *Ab = g_attn + (size_t)bk * NN * MM;
    const float *Vb = emV + (size_t)bk * MM * DD;

    float2 acc[4][4];
#pragma unroll
    for (int r = 0; r < 4; r++)
#pragma unroll
        for (int c = 0; c < 4; c++) acc[r][c] = make_float2(0.f, 0.f);

    for (int m0 = 0; m0 < MM; m0 += 32) {
#pragma unroll
        for (int i = 0; i < 2; i++) {   // A 64x32 -> transposed
            int idx = tid + i * 256;
            int row = idx >> 3, q = idx & 7;
            float4 v = *reinterpret_cast<const float4 *>(
                &Ab[(size_t)(n0 + row) * MM + m0 + q * 4]);
            AsT[q * 4 + 0][row] = v.x; AsT[q * 4 + 1][row] = v.y;
            AsT[q * 4 + 2][row] = v.z; AsT[q * 4 + 3][row] = v.w;
        }
#pragma unroll
        for (int i = 0; i < 4; i++) {   // V 32x128 direct float4
            int idx = tid + i * 256;
            int mm = idx >> 5, dq = idx & 31;
            float4 v = *reinterpret_cast<const float4 *>(
                &Vb[(size_t)(m0 + mm) * DD + dq * 4]);
            *reinterpret_cast<float4 *>(&Vs[mm][dq * 4]) = v;
        }
        __syncthreads();
#pragma unroll
        for (int mm = 0; mm < 32; mm++) {
            float4 a4 = *reinterpret_cast<const float4 *>(&AsT[mm][ty * 4]);
#pragma unroll
            for (int c = 0; c < 2; c++) {
                float4 v4 = *reinterpret_cast<const float4 *>(
                    &Vs[mm][tx * 4 + c * 64]);
                float2 vlo = make_float2(v4.x, v4.y);
                float2 vhi = make_float2(v4.z, v4.w);
                fma2(acc[0][c * 2],     make_float2(a4.x, a4.x), vlo);
                fma2(acc[0][c * 2 + 1], make_float2(a4.x, a4.x), vhi);
                fma2(acc[1][c * 2],     make_float2(a4.y, a4.y), vlo);
                fma2(acc[1][c * 2 + 1], make_float2(a4.y, a4.y), vhi);
                fma2(acc[2][c * 2],     make_float2(a4.z, a4.z), vlo);
                fma2(acc[2][c * 2 + 1], make_float2(a4.z, a4.z), vhi);
                fma2(acc[3][c * 2],     make_float2(a4.w, a4.w), vlo);
                fma2(acc[3][c * 2 + 1], make_float2(a4.w, a4.w), vhi);
            }
        }
        __syncthreads();
    }

    if (MODE == 0 || MODE == 1) {
        const float *w1k = w1 + k * DD, *w2k = w2 + k * DD, *gbk = gb + k * DD;
#pragma unroll
        for (int r = 0; r < 4; r++) {
            int n = n0 + ty * 4 + r;
            size_t yb = ((size_t)bk * NN + n) * DD;
#pragma unroll
            for (int c = 0; c < 2; c++) {
                int d = tx * 4 + c * 64;
                float del[4] = {acc[r][c * 2].x, acc[r][c * 2].y,
                                acc[r][c * 2 + 1].x, acc[r][c * 2 + 1].y};
                float4 yo = *reinterpret_cast<const float4 *>(&g_y[yb + d]);
                float4 w1v = *reinterpret_cast<const float4 *>(&w1k[d]);
                float4 w2v = *reinterpret_cast<const float4 *>(&w2k[d]);
                float4 gbv = *reinterpret_cast<const float4 *>(&gbk[d]);
                float yoa[4] = {yo.x, yo.y, yo.z, yo.w};
                float w1a[4] = {w1v.x, w1v.y, w1v.z, w1v.w};
                float w2a[4] = {w2v.x, w2v.y, w2v.z, w2v.w};
                float gba[4] = {gbv.x, gbv.y, gbv.z, gbv.w};
                float yn[4];
#pragma unroll
                for (int j = 0; j < 4; j++) {
                    float g = sigmoidf(w1a[j] * yoa[j] + w2a[j] * del[j] + gba[j]);
                    yn[j] = yoa[j] + g * del[j];
                }
                if (MODE == 0) {
                    *reinterpret_cast<float4 *>(&g_y[yb + d]) =
                        make_float4(yn[0], yn[1], yn[2], yn[3]);
                } else {
                    float4 sd = *reinterpret_cast<const float4 *>(
                        &seed[((size_t)b * NN + n) * DD + d]);
                    *reinterpret_cast<float4 *>(
                        &out[OFF_YEM + (((size_t)b * NN + n) * NB + k) * DD + d]) =
                        make_float4(yn[0] - sd.x, yn[1] - sd.y,
                                    yn[2] - sd.z, yn[3] - sd.w);
                }
            }
        }
    } else {  // MODE 2: recon epilogue
        float4 wcv[4][2];
        float psq[4] = {0.f, 0.f, 0.f, 0.f};
#pragma unroll
        for (int r = 0; r < 4; r++) {
            int n = n0 + ty * 4 + r;
#pragma unroll
            for (int c = 0; c < 2; c++) {
                int d = tx * 4 + c * 64;
                float4 w = *reinterpret_cast<const float4 *>(
                    &wcand[((size_t)b * NN + n) * DD + d]);
                wcv[r][c] = w;
                float r0 = w.x - acc[r][c * 2].x;
                float r1 = w.y - acc[r][c * 2].y;
                float r2 = w.z - acc[r][c * 2 + 1].x;
                float r3 = w.w - acc[r][c * 2 + 1].y;
                psq[r] += r0 * r0 + r1 * r1 + r2 * r2 + r3 * r3;
            }
        }
#pragma unroll
        for (int r = 0; r < 4; r++)
#pragma unroll
            for (int o = 8; o; o >>= 1)
                psq[r] += __shfl_xor_sync(0xffffffffu, psq[r], o);
        if (tx == 0) {
#pragma unroll
            for (int r = 0; r < 4; r++) {
                int n = n0 + ty * 4 + r;
                float err = sqrtf(psq[r]);
                float nv = 0.5f * g_surp[b * NN + n] + 0.5f * err;
                rownov[ty * 4 + r] = nv;
                g_nov[bk * NN + n] = nv;
            }
        }
        __syncthreads();
#pragma unroll
        for (int r = 0; r < 4; r++) {
            int n = n0 + ty * 4 + r;
            float nv = rownov[ty * 4 + r];
#pragma unroll
            for (int c = 0; c < 2; c++) {
                int d = tx * 4 + c * 64;
                float4 w = wcv[r][c];
                *reinterpret_cast<float4 *>(
                    &out[OFF_DEM + (((size_t)b * NN + n) * NB + k) * DD + d]) =
                    make_float4(nv * w.x, nv * w.y, nv * w.z, nv * w.w);
            }
        }
    }
}

// ---------------- update_K / update_V GEMM + sum_n weighted_route ------------
__global__ __launch_bounds__(256) void updkv_kernel(
    const float *__restrict__ wcand) {
    __shared__ __align__(16) float WRs[32][72];    // [n][m] tile
    __shared__ __align__(16) float Wn[32][132];
    __shared__ __align__(16) float Wc[32][132];
    __shared__ float novS[32];
    int bk = blockIdx.y, b = bk >> 3;
    int m0 = blockIdx.x * 64;
    int tid = threadIdx.x, ty = tid >> 4, tx = tid & 15;

    float2 aK[4][4], aV[4][4];
    float swr[4] = {0.f, 0.f, 0.f, 0.f};
#pragma unroll
    for (int r = 0; r < 4; r++)
#pragma unroll
        for (int c = 0; c < 4; c++) {
            aK[r][c] = make_float2(0.f, 0.f);
            aV[r][c] = make_float2(0.f, 0.f);
        }

    for (int n0 = 0; n0 < NN; n0 += 32) {
        if (tid < 32) novS[tid] = g_nov[bk * NN + n0 + tid];
#pragma unroll
        for (int i = 0; i < 2; i++) {   // route tile 32n x 64m, direct float4
            int idx = tid + i * 256;
            int nn = idx >> 4, q = idx & 15;
            float4 v = *reinterpret_cast<const float4 *>(
                &g_route[((size_t)bk * NN + n0 + nn) * MM + m0 + q * 4]);
            *reinterpret_cast<float4 *>(&WRs[nn][q * 4]) = v;
        }
#pragma unroll
        for (int i = 0; i < 4; i++) {   // wnorm / wcand tiles 32n x 128d
            int idx = tid + i * 256;
            int nn = idx >> 5, dq = idx & 31;
            size_t base = ((size_t)b * NN + n0 + nn) * DD + dq * 4;
            *reinterpret_cast<float4 *>(&Wn[nn][dq * 4]) =
                *reinterpret_cast<const float4 *>(&g_wnorm[base]);
            *reinterpret_cast<float4 *>(&Wc[nn][dq * 4]) =
                *reinterpret_cast<const float4 *>(&wcand[base]);
        }
        __syncthreads();
#pragma unroll 4
        for (int nn = 0; nn < 32; nn++) {
            float nv = novS[nn];
            float4 wr4 = *reinterpret_cast<const float4 *>(&WRs[nn][ty * 4]);
            float a0 = wr4.x * nv, a1 = wr4.y * nv;
            float a2 = wr4.z * nv, a3 = wr4.w * nv;
            swr[0] += a0; swr[1] += a1; swr[2] += a2; swr[3] += a3;
#pragma unroll
            for (int c = 0; c < 2; c++) {
                float4 wn4 = *reinterpret_cast<const float4 *>(
                    &Wn[nn][tx * 4 + c * 64]);
                float4 wc4 = *reinterpret_cast<const float4 *>(
                    &Wc[nn][tx * 4 + c * 64]);
                float2 nlo = make_float2(wn4.x, wn4.y), nhi = make_float2(wn4.z, wn4.w);
                float2 clo = make_float2(wc4.x, wc4.y), chi = make_float2(wc4.z, wc4.w);
                fma2(aK[0][c * 2],     make_float2(a0, a0), nlo);
                fma2(aK[0][c * 2 + 1], make_float2(a0, a0), nhi);
                fma2(aK[1][c * 2],     make_float2(a1, a1), nlo);
                fma2(aK[1][c * 2 + 1], make_float2(a1, a1), nhi);
                fma2(aK[2][c * 2],     make_float2(a2, a2), nlo);
                fma2(aK[2][c * 2 + 1], make_float2(a2, a2), nhi);
                fma2(aK[3][c * 2],     make_float2(a3, a3), nlo);
                fma2(aK[3][c * 2 + 1], make_float2(a3, a3), nhi);
                fma2(aV[0][c * 2],     make_float2(a0, a0), clo);
                fma2(aV[0][c * 2 + 1], make_float2(a0, a0), chi);
                fma2(aV[1][c * 2],     make_float2(a1, a1), clo);
                fma2(aV[1][c * 2 + 1], make_float2(a1, a1), chi);
                fma2(aV[2][c * 2],     make_float2(a2, a2), clo);
                fma2(aV[2][c * 2 + 1], make_float2(a2, a2), chi);
                fma2(aV[3][c * 2],     make_float2(a3, a3), clo);
                fma2(aV[3][c * 2 + 1], make_float2(a3, a3), chi);
            }
        }
        __syncthreads();
    }
#pragma unroll
    for (int r = 0; r < 4; r++) {
        int m = m0 + ty * 4 + r;
#pragma unroll
        for (int c = 0; c < 2; c++) {
            int d = tx * 4 + c * 64;
            size_t off = ((size_t)bk * MM + m) * DD + d;
            *reinterpret_cast<float4 *>(&g_updK[off]) =
                make_float4(aK[r][c * 2].x, aK[r][c * 2].y,
                            aK[r][c * 2 + 1].x, aK[r][c * 2 + 1].y);
            *reinterpret_cast<float4 *>(&g_updV[off]) =
                make_float4(aV[r][c * 2].x, aV[r][c * 2].y,
                            aV[r][c * 2 + 1].x, aV[r][c * 2 + 1].y);
        }
        if (tx == 0) g_sumwr[bk * MM + m] = swr[r];
    }
}

// ---------------- final: blend K/V, S budget, age -----------------------------
__global__ __launch_bounds__(256) void final_kernel(
    const float *__restrict__ emK, const float *__restrict__ emV,
    const float *__restrict__ emS, const float *__restrict__ emAge,
    const float *__restrict__ gem, float *__restrict__ out) {
    int bk = blockIdx.x, b = bk >> 3, k = bk & 7;
    int tid = threadIdx.x, warp = tid >> 5, lane = tid & 31;
    float ge = gem[b * NB + k];
    const float invN = 1.f / (float)NN;

    for (int m = warp; m < MM; m += 8) {
        float swv = g_sumwr[bk * MM + m];
        float denom = fmaxf(swv, 1e-8f);
        float alpha = fminf(ge * swv * invN, 1.f);
        float oma = 1.f - alpha;
        float idn = 1.f / denom;
        size_t off = ((size_t)bk * MM + m) * DD + lane * 4;
        float4 uk = *reinterpret_cast<const float4 *>(&g_updK[off]);
        uk.x *= idn; uk.y *= idn; uk.z *= idn; uk.w *= idn;
        float sq = uk.x * uk.x + uk.y * uk.y + uk.z * uk.z + uk.w * uk.w;
#pragma unroll
        for (int o = 16; o; o >>= 1) sq += __shfl_xor_sync(0xffffffffu, sq, o);
        float inv = 1.f / fmaxf(sqrtf(sq), 1e-12f);
        float ai = alpha * inv;
        float4 ek = *reinterpret_cast<const float4 *>(&emK[off]);
        float4 nk = make_float4(oma * ek.x + ai * uk.x, oma * ek.y + ai * uk.y,
                                oma * ek.z + ai * uk.z, oma * ek.w + ai * uk.w);
        *reinterpret_cast<float4 *>(&out[OFF_K + off]) = nk;
        float4 uv = *reinterpret_cast<const float4 *>(&g_updV[off]);
        uv.x *= idn; uv.y *= idn; uv.z *= idn; uv.w *= idn;
        float4 ev = *reinterpret_cast<const float4 *>(&emV[off]);
        float4 nv = make_float4(oma * ev.x + alpha * uv.x, oma * ev.y + alpha * uv.y,
                                oma * ev.z + alpha * uv.z, oma * ev.w + alpha * uv.w);
        *reinterpret_cast<float4 *>(&out[OFF_V + off]) = nv;
    }

    __shared__ float red[8];
    __shared__ float stot;
    float part = 0.f, sn[2], al[2];
#pragma unroll
    for (int i = 0; i < 2; i++) {
        int m = tid + i * 256;
        float swv = g_sumwr[bk * MM + m];
        al[i] = fminf(ge * swv * invN, 1.f);
        float v = emS[bk * MM + m] + al[i];
        v = fminf(fmaxf(v, 0.f), 3.0f);
        sn[i] = v; part += v;
    }
#pragma unroll
    for (int o = 16; o; o >>= 1) part += __shfl_xor_sync(0xffffffffu, part, o);
    if (lane == 0) red[warp] = part;
    __syncthreads();
    if (tid == 0) {
        float t = 0.f;
        for (int i = 0; i < 8; i++) t += red[i];
        stot = t;
    }
    __syncthreads();
    float scale = fminf(1.f, 32.0f / fmaxf(stot, 1e-8f));
#pragma unroll
    for (int i = 0; i < 2; i++) {
        int m = tid + i * 256;
        out[OFF_S + bk * MM + m] = sn[i] * scale;
        out[OFF_AGE + bk * MM + m] = emAge[bk * MM + m] * (1.f - al[i]);
    }
}

// ---------------- launcher -----------------------------------------------------
extern "C" void kernel_launch(void *const *d_in, const int *in_sizes, int n_in,
                              void *d_out, int out_size) {
    const float *seed     = (const float *)d_in[0];
    const float *wcand    = (const float *)d_in[1];
    const float *surprise = (const float *)d_in[2];
    const float *gem      = (const float *)d_in[3];
    const float *emK      = (const float *)d_in[4];
    const float *emV      = (const float *)d_in[5];
    const float *emS      = (const float *)d_in[6];
    const float *emAge    = (const float *)d_in[7];
    const float *w1       = (const float *)d_in[8];
    const float *w2       = (const float *)d_in[9];
    const float *gb       = (const float *)d_in[10];
    const float *rtau     = (const float *)d_in[11];
    const float *rtauw    = (const float *)d_in[12];
    float *out = (float *)d_out;

    dim3 gA(32, 64), gB(16, 64), gU(8, 64);
    dim3 gT(16, 4, 64), bT(32, 8);

    transpose_k_kernel<<<gT, bT>>>(emK);
    init_y_kernel<<<8192, 256>>>(seed);
    wnorm_kernel<<<8192, 128>>>(wcand, surprise);

    // step 0
    scores_kernel<0><<<gA, 256>>>(emS, rtau, rtauw);
    av_kernel<0><<<gB, 256>>>(emV, w1, w2, gb, seed, wcand, out);
    // step 1 (last)
    scores_kernel<0><<<gA, 256>>>(emS, rtau, rtauw);
    av_kernel<1><<<gB, 256>>>(emV, w1, w2, gb, seed, wcand, out);

    // novelty scores -> nov_attn + route
    scores_kernel<1><<<gA, 256>>>(emS, rtau, rtauw);
    // recon + novelty + delta_em
    av_kernel<2><<<gB, 256>>>(emV, w1, w2, gb, seed, wcand, out);
    // update_K / update_V
    updkv_kernel<<<gU, 256>>>(wcand);
    // final blend / budget
    final_kernel<<<64, 256>>>(emK, emV, emS, emAge, gem, out);
}

// round 4
// speedup vs baseline: 1.0933x; 1.0791x over previous
#include <cuda_runtime.h>
#include <math.h>

#define BSZ 8
#define NB  8
#define MM  512
#define DD  128
#define NN  1024
#define NBK 64
#define NEGV (-1e30f)

#define OFF_YEM 0
#define OFF_DEM 8388608
#define OFF_K   16777216
#define OFF_V   20971520
#define OFF_S   25165824
#define OFF_AGE 25198592

// ---------------- scratch -----------------------------------------------------
__device__ float g_y[NBK * NN * DD];
__device__ float g_attn[NBK * NN * MM];    // UNNORMALIZED exp
__device__ float g_route[NBK * NN * MM];   // UNNORMALIZED exp
__device__ float g_wnorm[BSZ * NN * DD];
__device__ float g_surp[BSZ * NN];
__device__ float g_nov[NBK * NN];
__device__ float g_rsA[NBK * NN];          // has / rowsum(attn exp)
__device__ float g_rsR[NBK * NN];          // 1 / rowsum(route exp)
__device__ float g_updK[NBK * MM * DD];
__device__ float g_updV[NBK * MM * DD];
__device__ float g_Kt[NBK * DD * MM];      // em_K transposed (bk, d, m)
__device__ float g_WnS[NBK * NN * DD];     // nov' * w_norm   (bk, n, d)
__device__ float g_WcS[NBK * NN * DD];     // nov' * w_cand
__device__ float g_swrP[4 * NBK * MM];     // partial sums of weighted_route

// ---------------- helpers -----------------------------------------------------
__device__ __forceinline__ void fma2(float2 &d, float2 a, float2 b) {
    asm("fma.rn.f32x2 %0, %1, %2, %0;"
        : "+l"(*reinterpret_cast<unsigned long long *>(&d))
        : "l"(*reinterpret_cast<unsigned long long *>(&a)),
          "l"(*reinterpret_cast<unsigned long long *>(&b)));
}
__device__ __forceinline__ float softplusf(float x) {
    return (x > 20.f) ? x : log1pf(expf(x));
}
__device__ __forceinline__ float sigmoidf(float x) {
    return 1.f / (1.f + __expf(-x));
}

// ---------------- K transpose --------------------------------------------------
__global__ void transpose_k_kernel(const float *__restrict__ emK) {
    __shared__ float t[32][33];
    int bk = blockIdx.z;
    int m0 = blockIdx.x * 32, d0 = blockIdx.y * 32;
    int x = threadIdx.x, y0 = threadIdx.y;
#pragma unroll
    for (int yy = 0; yy < 32; yy += 8)
        t[y0 + yy][x] = emK[((size_t)bk * MM + m0 + y0 + yy) * DD + d0 + x];
    __syncthreads();
#pragma unroll
    for (int yy = 0; yy < 32; yy += 8)
        g_Kt[((size_t)bk * DD + d0 + y0 + yy) * MM + m0 + x] = t[x][y0 + yy];
}

// ---------------- y init --------------------------------------------------------
__global__ void init_y_kernel(const float *__restrict__ seed) {
    int i = blockIdx.x * 256 + threadIdx.x;
    int bk = i >> 15;
    int rem = i & 32767;
    int b = bk >> 3;
    reinterpret_cast<float4 *>(g_y)[i] =
        reinterpret_cast<const float4 *>(seed)[b * 32768 + rem];
}

// ---------------- w_norm + surprise magnitude -----------------------------------
__global__ void wnorm_kernel(const float *__restrict__ wc,
                             const float *__restrict__ sp) {
    int row = blockIdx.x;
    int tid = threadIdx.x;
    float w = wc[row * DD + tid];
    float s = sp[row * DD + tid];
    float a = w * w, bb = s * s;
#pragma unroll
    for (int o = 16; o; o >>= 1) {
        a  += __shfl_xor_sync(0xffffffffu, a, o);
        bb += __shfl_xor_sync(0xffffffffu, bb, o);
    }
    __shared__ float ra[4], rb[4];
    if ((tid & 31) == 0) { ra[tid >> 5] = a; rb[tid >> 5] = bb; }
    __syncthreads();
    float na = ra[0] + ra[1] + ra[2] + ra[3];
    float nb = rb[0] + rb[1] + rb[2] + rb[3];
    g_wnorm[row * DD + tid] = w / fmaxf(sqrtf(na), 1e-12f);
    if (tid == 0) g_surp[row] = sqrtf(nb);
}

// ---------------- scores GEMM + masked exp (unnormalized) -----------------------
// block: 32 n x 512 m. 8 warps: rg=wid&3 (8 rows each), ch=wid>>2 (256-col half).
// lane tx covers m = ch*256 + c*128 + tx*4 + j (c=0,1; j=0..3).
template <int MODE>
__global__ __launch_bounds__(256, 2) void scores_kernel(
    const float *__restrict__ emS,
    const float *__restrict__ rtau, const float *__restrict__ rtauw) {
    __shared__ __align__(16) float AsT[16][36];
    __shared__ __align__(16) float Bs[16][520];
    __shared__ float smMax[2][32], smSum[2][32];
    __shared__ int sHas;
    int bk = blockIdx.y, b = bk >> 3, k = bk & 7;
    int n0 = blockIdx.x * 32;
    int tid = threadIdx.x, wid = tid >> 5, tx = tid & 31;
    int rg = wid & 3, ch = wid >> 2;
    if (tid == 0) sHas = 0;

    const float *Yb = (MODE == 0) ? (g_y + (size_t)bk * NN * DD)
                                  : (g_wnorm + (size_t)b * NN * DD);
    const float *Ktb = g_Kt + (size_t)bk * DD * MM;

    float2 acc[8][4];
#pragma unroll
    for (int r = 0; r < 8; r++)
#pragma unroll
        for (int c = 0; c < 4; c++) acc[r][c] = make_float2(0.f, 0.f);

    for (int dc = 0; dc < 8; dc++) {
        int d0 = dc * 16;
        if (tid < 128) {    // A: 32 rows x 16 d, transposed store
            int row = tid >> 2, dl = (tid & 3) * 4;
            float4 v = *reinterpret_cast<const float4 *>(
                &Yb[(n0 + row) * DD + d0 + dl]);
            AsT[dl][row] = v.x; AsT[dl + 1][row] = v.y;
            AsT[dl + 2][row] = v.z; AsT[dl + 3][row] = v.w;
        }
#pragma unroll
        for (int i = 0; i < 8; i++) {   // B: 16 d x 512 m
            int idx = tid + i * 256;
            int q = idx >> 7, mq = idx & 127;
            *reinterpret_cast<float4 *>(&Bs[q][mq * 4]) =
                *reinterpret_cast<const float4 *>(
                    &Ktb[(size_t)(d0 + q) * MM + mq * 4]);
        }
        __syncthreads();
#pragma unroll
        for (int kk = 0; kk < 16; kk++) {
            float4 alo = *reinterpret_cast<const float4 *>(&AsT[kk][rg * 8]);
            float4 ahi = *reinterpret_cast<const float4 *>(&AsT[kk][rg * 8 + 4]);
            float ar[8] = {alo.x, alo.y, alo.z, alo.w,
                           ahi.x, ahi.y, ahi.z, ahi.w};
#pragma unroll
            for (int c = 0; c < 2; c++) {
                float4 bv = *reinterpret_cast<const float4 *>(
                    &Bs[kk][ch * 256 + c * 128 + tx * 4]);
                float2 blo = make_float2(bv.x, bv.y);
                float2 bhi = make_float2(bv.z, bv.w);
#pragma unroll
                for (int r = 0; r < 8; r++) {
                    fma2(acc[r][c * 2],     make_float2(ar[r], ar[r]), blo);
                    fma2(acc[r][c * 2 + 1], make_float2(ar[r], ar[r]), bhi);
                }
            }
        }
        __syncthreads();
    }

    // ---- epilogue
    float inv_tau  = 1.f / (softplusf(rtau[k]) + 0.1f);
    float inv_tauw = 1.f / (softplusf(rtauw[k]) + 0.1f);
    const float *Sb = emS + bk * MM;
    bool actf[8]; bool myany = false;
#pragma unroll
    for (int c = 0; c < 2; c++) {
        float4 s4 = *reinterpret_cast<const float4 *>(
            &Sb[ch * 256 + c * 128 + tx * 4]);
        actf[c * 4 + 0] = s4.x > 0.f; actf[c * 4 + 1] = s4.y > 0.f;
        actf[c * 4 + 2] = s4.z > 0.f; actf[c * 4 + 3] = s4.w > 0.f;
        myany |= actf[c * 4] | actf[c * 4 + 1] | actf[c * 4 + 2] | actf[c * 4 + 3];
    }
    if (__ballot_sync(0xffffffffu, myany) && tx == 0) sHas = 1;

    int np = (MODE == 1) ? 2 : 1;
    for (int p = 0; p < np; p++) {
        float sc = (p == 0) ? inv_tau : inv_tauw;
        float *op = (p == 0) ? g_attn : g_route;
        float lmax[8];
#pragma unroll
        for (int r = 0; r < 8; r++) {
            float vv[8];
            vv[0] = actf[0] ? acc[r][0].x * sc : NEGV;
            vv[1] = actf[1] ? acc[r][0].y * sc : NEGV;
            vv[2] = actf[2] ? acc[r][1].x * sc : NEGV;
            vv[3] = actf[3] ? acc[r][1].y * sc : NEGV;
            vv[4] = actf[4] ? acc[r][2].x * sc : NEGV;
            vv[5] = actf[5] ? acc[r][2].y * sc : NEGV;
            vv[6] = actf[6] ? acc[r][3].x * sc : NEGV;
            vv[7] = actf[7] ? acc[r][3].y * sc : NEGV;
            float m = vv[0];
#pragma unroll
            for (int j = 1; j < 8; j++) m = fmaxf(m, vv[j]);
#pragma unroll
            for (int o = 16; o; o >>= 1)
                m = fmaxf(m, __shfl_xor_sync(0xffffffffu, m, o));
            lmax[r] = m;
        }
        if (tx == 0)
#pragma unroll
            for (int r = 0; r < 8; r++) smMax[ch][rg * 8 + r] = lmax[r];
        __syncthreads();
#pragma unroll
        for (int r = 0; r < 8; r++) {
            int row = rg * 8 + r;
            float gmx = fmaxf(smMax[0][row], smMax[1][row]);
            float vv[8];
            vv[0] = actf[0] ? acc[r][0].x * sc : NEGV;
            vv[1] = actf[1] ? acc[r][0].y * sc : NEGV;
            vv[2] = actf[2] ? acc[r][1].x * sc : NEGV;
            vv[3] = actf[3] ? acc[r][1].y * sc : NEGV;
            vv[4] = actf[4] ? acc[r][2].x * sc : NEGV;
            vv[5] = actf[5] ? acc[r][2].y * sc : NEGV;
            vv[6] = actf[6] ? acc[r][3].x * sc : NEGV;
            vv[7] = actf[7] ? acc[r][3].y * sc : NEGV;
            float ps = 0.f;
#pragma unroll
            for (int j = 0; j < 8; j++) { vv[j] = __expf(vv[j] - gmx); ps += vv[j]; }
#pragma unroll
            for (int o = 16; o; o >>= 1)
                ps += __shfl_xor_sync(0xffffffffu, ps, o);
            if (tx == 0) smSum[ch][row] = ps;
            size_t rowoff = ((size_t)bk * NN + n0 + row) * MM + ch * 256;
            *reinterpret_cast<float4 *>(&op[rowoff + tx * 4]) =
                make_float4(vv[0], vv[1], vv[2], vv[3]);
            *reinterpret_cast<float4 *>(&op[rowoff + 128 + tx * 4]) =
                make_float4(vv[4], vv[5], vv[6], vv[7]);
        }
        __syncthreads();
        if (tid < 32) {
            float rs = smSum[0][tid] + smSum[1][tid];
            float inv = 1.f / rs;
            size_t idx = (size_t)bk * NN + n0 + tid;
            if (p == 0) g_rsA[idx] = sHas ? inv : 0.f;
            else        g_rsR[idx] = inv;
        }
    }
}

// ---------------- A@V GEMM ------------------------------------------------------
// block: 128 n x 128 d; 8 warps x 16 rows; lane d = tx*4.
template <int MODE>
__global__ __launch_bounds__(256, 2) void av_kernel(
    const float *__restrict__ emV, const float *__restrict__ w1,
    const float *__restrict__ w2, const float *__restrict__ gb,
    const float *__restrict__ seed, const float *__restrict__ wcand,
    float *__restrict__ out) {
    __shared__ __align__(16) float AsT[32][132];   // [m][row]
    __shared__ __align__(16) float Vs[32][132];    // [m][d]
    int bk = blockIdx.y, b = bk >> 3, k = bk & 7;
    int n0 = blockIdx.x * 128;
    int tid = threadIdx.x, wid = tid >> 5, tx = tid & 31;
    const float *Ab = g_attn + (size_t)bk * NN * MM;
    const float *Vb = emV + (size_t)bk * MM * DD;

    float2 acc[16][2];
#pragma unroll
    for (int r = 0; r < 16; r++) {
        acc[r][0] = make_float2(0.f, 0.f);
        acc[r][1] = make_float2(0.f, 0.f);
    }

    for (int m0 = 0; m0 < MM; m0 += 32) {
#pragma unroll
        for (int i = 0; i < 4; i++) {   // A 128 rows x 32 m, transposed
            int idx = tid + i * 256;
            int row = idx >> 3, q = idx & 7;
            float4 v = *reinterpret_cast<const float4 *>(
                &Ab[(size_t)(n0 + row) * MM + m0 + q * 4]);
            AsT[q * 4 + 0][row] = v.x; AsT[q * 4 + 1][row] = v.y;
            AsT[q * 4 + 2][row] = v.z; AsT[q * 4 + 3][row] = v.w;
        }
#pragma unroll
        for (int i = 0; i < 4; i++) {   // V 32 m x 128 d
            int idx = tid + i * 256;
            int mm = idx >> 5, dq = idx & 31;
            *reinterpret_cast<float4 *>(&Vs[mm][dq * 4]) =
                *reinterpret_cast<const float4 *>(
                    &Vb[(size_t)(m0 + mm) * DD + dq * 4]);
        }
        __syncthreads();
#pragma unroll
        for (int mm = 0; mm < 32; mm++) {
            float4 a0 = *reinterpret_cast<const float4 *>(&AsT[mm][wid * 16]);
            float4 a1 = *reinterpret_cast<const float4 *>(&AsT[mm][wid * 16 + 4]);
            float4 a2 = *reinterpret_cast<const float4 *>(&AsT[mm][wid * 16 + 8]);
            float4 a3 = *reinterpret_cast<const float4 *>(&AsT[mm][wid * 16 + 12]);
            float ar[16] = {a0.x, a0.y, a0.z, a0.w, a1.x, a1.y, a1.z, a1.w,
                            a2.x, a2.y, a2.z, a2.w, a3.x, a3.y, a3.z, a3.w};
            float4 v4 = *reinterpret_cast<const float4 *>(&Vs[mm][tx * 4]);
            float2 vlo = make_float2(v4.x, v4.y);
            float2 vhi = make_float2(v4.z, v4.w);
#pragma unroll
            for (int r = 0; r < 16; r++) {
                fma2(acc[r][0], make_float2(ar[r], ar[r]), vlo);
                fma2(acc[r][1], make_float2(ar[r], ar[r]), vhi);
            }
        }
        __syncthreads();
    }

    int rowbase = n0 + wid * 16;
    int d = tx * 4;

    if (MODE == 0 || MODE == 1) {
        const float4 w1v = *reinterpret_cast<const float4 *>(&w1[k * DD + d]);
        const float4 w2v = *reinterpret_cast<const float4 *>(&w2[k * DD + d]);
        const float4 gbv = *reinterpret_cast<const float4 *>(&gb[k * DD + d]);
#pragma unroll
        for (int r = 0; r < 16; r++) {
            int n = rowbase + r;
            float s = g_rsA[(size_t)bk * NN + n];
            size_t yb = ((size_t)bk * NN + n) * DD + d;
            float4 yo = *reinterpret_cast<const float4 *>(&g_y[yb]);
            float dl0 = s * acc[r][0].x, dl1 = s * acc[r][0].y;
            float dl2 = s * acc[r][1].x, dl3 = s * acc[r][1].y;
            float g0 = sigmoidf(w1v.x * yo.x + w2v.x * dl0 + gbv.x);
            float g1 = sigmoidf(w1v.y * yo.y + w2v.y * dl1 + gbv.y);
            float g2 = sigmoidf(w1v.z * yo.z + w2v.z * dl2 + gbv.z);
            float g3 = sigmoidf(w1v.w * yo.w + w2v.w * dl3 + gbv.w);
            float4 yn = make_float4(yo.x + g0 * dl0, yo.y + g1 * dl1,
                                    yo.z + g2 * dl2, yo.w + g3 * dl3);
            if (MODE == 0) {
                *reinterpret_cast<float4 *>(&g_y[yb]) = yn;
            } else {
                float4 sd = *reinterpret_cast<const float4 *>(
                    &seed[((size_t)b * NN + n) * DD + d]);
                *reinterpret_cast<float4 *>(
                    &out[OFF_YEM + (((size_t)b * NN + n) * NB + k) * DD + d]) =
                    make_float4(yn.x - sd.x, yn.y - sd.y, yn.z - sd.z, yn.w - sd.w);
            }
        }
    } else {  // MODE 2: recon + novelty + delta_em + scaled Wn/Wc
        float psq[16];
#pragma unroll
        for (int r = 0; r < 16; r++) {
            int n = rowbase + r;
            float s = g_rsA[(size_t)bk * NN + n];
            float4 w = *reinterpret_cast<const float4 *>(
                &wcand[((size_t)b * NN + n) * DD + d]);
            float r0 = w.x - s * acc[r][0].x;
            float r1 = w.y - s * acc[r][0].y;
            float r2 = w.z - s * acc[r][1].x;
            float r3 = w.w - s * acc[r][1].y;
            psq[r] = r0 * r0 + r1 * r1 + r2 * r2 + r3 * r3;
        }
#pragma unroll
        for (int r = 0; r < 16; r++)
#pragma unroll
            for (int o = 16; o; o >>= 1)
                psq[r] += __shfl_xor_sync(0xffffffffu, psq[r], o);
#pragma unroll
        for (int r = 0; r < 16; r++) {
            int n = rowbase + r;
            float nv = 0.5f * g_surp[b * NN + n] + 0.5f * sqrtf(psq[r]);
            if (tx == 0) g_nov[bk * NN + n] = nv;
            float rsR = g_rsR[(size_t)bk * NN + n];
            float4 w = *reinterpret_cast<const float4 *>(
                &wcand[((size_t)b * NN + n) * DD + d]);
            float4 wn = *reinterpret_cast<const float4 *>(
                &g_wnorm[((size_t)b * NN + n) * DD + d]);
            float4 dem = make_float4(nv * w.x, nv * w.y, nv * w.z, nv * w.w);
            *reinterpret_cast<float4 *>(
                &out[OFF_DEM + (((size_t)b * NN + n) * NB + k) * DD + d]) = dem;
            size_t so = ((size_t)bk * NN + n) * DD + d;
            *reinterpret_cast<float4 *>(&g_WcS[so]) =
                make_float4(rsR * dem.x, rsR * dem.y, rsR * dem.z, rsR * dem.w);
            float np = nv * rsR;
            *reinterpret_cast<float4 *>(&g_WnS[so]) =
                make_float4(np * wn.x, np * wn.y, np * wn.z, np * wn.w);
        }
    }
}

// ---------------- swr partial: sum_n nov'*exp_route ------------------------------
__global__ __launch_bounds__(256) void swr_kernel() {
    int bk = blockIdx.x, chunk = blockIdx.y;
    int t = threadIdx.x;
    float2 acc = make_float2(0.f, 0.f);
#pragma unroll 4
    for (int i = 0; i < 256; i++) {
        int n = chunk * 256 + i;
        float novp = g_nov[bk * NN + n] * g_rsR[bk * NN + n];
        float2 e = *reinterpret_cast<const float2 *>(
            &g_route[((size_t)bk * NN + n) * MM + t * 2]);
        acc.x += novp * e.x;
        acc.y += novp * e.y;
    }
    *reinterpret_cast<float2 *>(&g_swrP[(chunk * NBK + bk) * MM + t * 2]) = acc;
}

// ---------------- update_K / update_V pure GEMM ----------------------------------
// block: 64 m x 128 d; 8 warps x 8 m-rows; lane d = tx*4.
__global__ __launch_bounds__(256, 2) void updkv_kernel() {
    __shared__ __align__(16) float WRs[32][72];    // exp_route [n][m]
    __shared__ __align__(16) float WnSs[32][132];  // [n][d]
    __shared__ __align__(16) float WcSs[32][132];
    int bk = blockIdx.y;
    int m0 = blockIdx.x * 64;
    int tid = threadIdx.x, wid = tid >> 5, tx = tid & 31;

    float2 aK[8][2], aV[8][2];
#pragma unroll
    for (int r = 0; r < 8; r++) {
        aK[r][0] = make_float2(0.f, 0.f); aK[r][1] = make_float2(0.f, 0.f);
        aV[r][0] = make_float2(0.f, 0.f); aV[r][1] = make_float2(0.f, 0.f);
    }

    for (int n0 = 0; n0 < NN; n0 += 32) {
#pragma unroll
        for (int i = 0; i < 2; i++) {   // route tile 32n x 64m
            int idx = tid + i * 256;
            int nn = idx >> 4, q = idx & 15;
            *reinterpret_cast<float4 *>(&WRs[nn][q * 4]) =
                *reinterpret_cast<const float4 *>(
                    &g_route[((size_t)bk * NN + n0 + nn) * MM + m0 + q * 4]);
        }
#pragma unroll
        for (int i = 0; i < 4; i++) {   // WnS/WcS tiles 32n x 128d
            int idx = tid + i * 256;
            int nn = idx >> 5, dq = idx & 31;
            size_t base = ((size_t)bk * NN + n0 + nn) * DD + dq * 4;
            *reinterpret_cast<float4 *>(&WnSs[nn][dq * 4]) =
                *reinterpret_cast<const float4 *>(&g_WnS[base]);
            *reinterpret_cast<float4 *>(&WcSs[nn][dq * 4]) =
                *reinterpret_cast<const float4 *>(&g_WcS[base]);
        }
        __syncthreads();
#pragma unroll
        for (int nn = 0; nn < 32; nn++) {
            float4 e0 = *reinterpret_cast<const float4 *>(&WRs[nn][wid * 8]);
            float4 e1 = *reinterpret_cast<const float4 *>(&WRs[nn][wid * 8 + 4]);
            float er[8] = {e0.x, e0.y, e0.z, e0.w, e1.x, e1.y, e1.z, e1.w};
            float4 wn = *reinterpret_cast<const float4 *>(&WnSs[nn][tx * 4]);
            float4 wc = *reinterpret_cast<const float4 *>(&WcSs[nn][tx * 4]);
            float2 nlo = make_float2(wn.x, wn.y), nhi = make_float2(wn.z, wn.w);
            float2 clo = make_float2(wc.x, wc.y), chi = make_float2(wc.z, wc.w);
#pragma unroll
            for (int r = 0; r < 8; r++) {
                float2 ep = make_float2(er[r], er[r]);
                fma2(aK[r][0], ep, nlo);
                fma2(aK[r][1], ep, nhi);
                fma2(aV[r][0], ep, clo);
                fma2(aV[r][1], ep, chi);
            }
        }
        __syncthreads();
    }
#pragma unroll
    for (int r = 0; r < 8; r++) {
        int m = m0 + wid * 8 + r;
        size_t off = ((size_t)bk * MM + m) * DD + tx * 4;
        *reinterpret_cast<float4 *>(&g_updK[off]) =
            make_float4(aK[r][0].x, aK[r][0].y, aK[r][1].x, aK[r][1].y);
        *reinterpret_cast<float4 *>(&g_updV[off]) =
            make_float4(aV[r][0].x, aV[r][0].y, aV[r][1].x, aV[r][1].y);
    }
}

// ---------------- final: blend K/V, S budget, age ---------------------------------
__global__ __launch_bounds__(256) void final_kernel(
    const float *__restrict__ emK, const float *__restrict__ emV,
    const float *__restrict__ emS, const float *__restrict__ emAge,
    const float *__restrict__ gem, float *__restrict__ out) {
    int bk = blockIdx.x, b = bk >> 3, k = bk & 7;
    int tid = threadIdx.x, warp = tid >> 5, lane = tid & 31;
    float ge = gem[b * NB + k];
    const float invN = 1.f / (float)NN;

    for (int m = warp; m < MM; m += 8) {
        float swv = g_swrP[bk * MM + m] + g_swrP[NBK * MM + bk * MM + m]
                  + g_swrP[2 * NBK * MM + bk * MM + m]
                  + g_swrP[3 * NBK * MM + bk * MM + m];
        float denom = fmaxf(swv, 1e-8f);
        float alpha = fminf(ge * swv * invN, 1.f);
        float oma = 1.f - alpha;
        float idn = 1.f / denom;
        size_t off = ((size_t)bk * MM + m) * DD + lane * 4;
        float4 uk = *reinterpret_cast<const float4 *>(&g_updK[off]);
        uk.x *= idn; uk.y *= idn; uk.z *= idn; uk.w *= idn;
        float sq = uk.x * uk.x + uk.y * uk.y + uk.z * uk.z + uk.w * uk.w;
#pragma unroll
        for (int o = 16; o; o >>= 1) sq += __shfl_xor_sync(0xffffffffu, sq, o);
        float inv = 1.f / fmaxf(sqrtf(sq), 1e-12f);
        float ai = alpha * inv;
        float4 ek = *reinterpret_cast<const float4 *>(&emK[off]);
        *reinterpret_cast<float4 *>(&out[OFF_K + off]) =
            make_float4(oma * ek.x + ai * uk.x, oma * ek.y + ai * uk.y,
                        oma * ek.z + ai * uk.z, oma * ek.w + ai * uk.w);
        float4 uv = *reinterpret_cast<const float4 *>(&g_updV[off]);
        uv.x *= idn; uv.y *= idn; uv.z *= idn; uv.w *= idn;
        float4 ev = *reinterpret_cast<const float4 *>(&emV[off]);
        *reinterpret_cast<float4 *>(&out[OFF_V + off]) =
            make_float4(oma * ev.x + alpha * uv.x, oma * ev.y + alpha * uv.y,
                        oma * ev.z + alpha * uv.z, oma * ev.w + alpha * uv.w);
    }

    __shared__ float red[8];
    __shared__ float stot;
    float part = 0.f, sn[2], al[2];
#pragma unroll
    for (int i = 0; i < 2; i++) {
        int m = tid + i * 256;
        float swv = g_swrP[bk * MM + m] + g_swrP[NBK * MM + bk * MM + m]
                  + g_swrP[2 * NBK * MM + bk * MM + m]
                  + g_swrP[3 * NBK * MM + bk * MM + m];
        al[i] = fminf(ge * swv * invN, 1.f);
        float v = emS[bk * MM + m] + al[i];
        v = fminf(fmaxf(v, 0.f), 3.0f);
        sn[i] = v; part += v;
    }
#pragma unroll
    for (int o = 16; o; o >>= 1) part += __shfl_xor_sync(0xffffffffu, part, o);
    if (lane == 0) red[warp] = part;
    __syncthreads();
    if (tid == 0) {
        float t = 0.f;
        for (int i = 0; i < 8; i++) t += red[i];
        stot = t;
    }
    __syncthreads();
    float scale = fminf(1.f, 32.0f / fmaxf(stot, 1e-8f));
#pragma unroll
    for (int i = 0; i < 2; i++) {
        int m = tid + i * 256;
        out[OFF_S + bk * MM + m] = sn[i] * scale;
        out[OFF_AGE + bk * MM + m] = emAge[bk * MM + m] * (1.f - al[i]);
    }
}

// ---------------- launcher ---------------------------------------------------------
extern "C" void kernel_launch(void *const *d_in, const int *in_sizes, int n_in,
                              void *d_out, int out_size) {
    const float *seed     = (const float *)d_in[0];
    const float *wcand    = (const float *)d_in[1];
    const float *surprise = (const float *)d_in[2];
    const float *gem      = (const float *)d_in[3];
    const float *emK      = (const float *)d_in[4];
    const float *emV      = (const float *)d_in[5];
    const float *emS      = (const float *)d_in[6];
    const float *emAge    = (const float *)d_in[7];
    const float *w1       = (const float *)d_in[8];
    const float *w2       = (const float *)d_in[9];
    const float *gb       = (const float *)d_in[10];
    const float *rtau     = (const float *)d_in[11];
    const float *rtauw    = (const float *)d_in[12];
    float *out = (float *)d_out;

    dim3 gA(32, 64), gB(8, 64), gU(8, 64);
    dim3 gT(16, 4, 64), bT(32, 8);

    transpose_k_kernel<<<gT, bT>>>(emK);
    init_y_kernel<<<8192, 256>>>(seed);
    wnorm_kernel<<<8192, 128>>>(wcand, surprise);

    scores_kernel<0><<<gA, 256>>>(emS, rtau, rtauw);
    av_kernel<0><<<gB, 256>>>(emV, w1, w2, gb, seed, wcand, out);
    scores_kernel<0><<<gA, 256>>>(emS, rtau, rtauw);
    av_kernel<1><<<gB, 256>>>(emV, w1, w2, gb, seed, wcand, out);

    scores_kernel<1><<<gA, 256>>>(emS, rtau, rtauw);
    av_kernel<2><<<gB, 256>>>(emV, w1, w2, gb, seed, wcand, out);

    swr_kernel<<<dim3(64, 4), 256>>>();
    updkv_kernel<<<gU, 256>>>();
    final_kernel<<<64, 256>>>(emK, emV, emS, emAge, gem, out);
}